// round 10
// baseline (speedup 1.0000x reference)
#include <cuda_runtime.h>
#include <cuda_bf16.h>
#include <cstdint>

#define HH   256
#define WW   256
#define NP   (HH * WW)
#define NG   1024
#define MM   50
#define NCH  150
#define ROWF 160                // padded feature row: 4 quarters x 40 floats
#define TPX  16                 // tile width
#define TPY  4                  // tile height
#define NTX  (WW / TPX)         // 16
#define NTY  (HH / TPY)         // 64
#define NTILES (NTX * NTY)      // 1024
#define CHUNK 16                // gaussians staged per chunk
#define TRB  150                // transpose blocks (150*256*4 = 153600)
#define CULLB (NTILES / 8)      // 128 cull blocks (8 tiles each)
#define RGRID 444               // persistent render CTAs (148 SM x 3)

// Scratch (device globals; no allocation allowed)
__device__ float g_params[NG * 8];                 // cx, cy, c1, c2, c3, op
__device__ __align__(16) float g_featT[NG * ROWF]; // [n][160] quarter-padded
__device__ short g_list[NTILES][NG];               // per-tile ordered lists
__device__ int   g_count[NTILES];
__device__ int   g_ticket;                         // dynamic tile ticket

// ---------------------------------------------------------------------------
__device__ __forceinline__ void project(int n,
        const float* __restrict__ xyz, const float* __restrict__ chol,
        const float* __restrict__ opac,
        float& cx, float& cy, float& c1, float& c2, float& c3, float& op,
        float4& bb) {
    float2 xr = ((const float2*)xyz)[n];
    float x  = tanhf(xr.x);
    float y  = tanhf(xr.y);
    float l1 = chol[3 * n + 0] + 0.5f;
    float l2 = chol[3 * n + 1];
    float l3 = chol[3 * n + 2] + 0.5f;
    float a = l1 * l1;
    float b = l1 * l2;
    float c = l2 * l2 + l3 * l3;
    float det = a * c - b * b;
    c1 = c / det;
    c2 = -b / det;
    c3 = a / det;
    cx = 0.5f * ((x + 1.0f) * (float)WW - 1.0f);
    cy = 0.5f * ((y + 1.0f) * (float)HH - 1.0f);
    op = opac[n];
    // alpha >= 1/255 <=> sigma <= T = ln(255*op); ellipse extents + margin
    float T = __logf(255.0f * op);
    if (T > 0.0f) {
        float hx = sqrtf(2.0f * T * a) + 2.0f;
        float hy = sqrtf(2.0f * T * c) + 2.0f;
        bb = make_float4(cx - hx, cx + hx, cy - hy, cy + hy);
    } else {
        bb = make_float4(1e9f, -1e9f, 1e9f, -1e9f);
    }
}

// ---------------------------------------------------------------------------
// Kernel A: blocks [0,150)  feature transpose (quarter-padded rows, MLP=4);
//           blocks [150,278) project-in-SMEM + warp-per-tile cull;
//           cull block 0 persists params, zeroes padding, resets ticket.
// ---------------------------------------------------------------------------
__global__ void prep_and_cull(const float* __restrict__ xyz,
                              const float* __restrict__ chol,
                              const float* __restrict__ opac,
                              const float* __restrict__ fdc,
                              const int*   __restrict__ cid_p) {
    const int tid = threadIdx.x;
    if (blockIdx.x < TRB) {
        const int cid = *cid_p;
#pragma unroll
        for (int k = 0; k < 4; k++) {
            int i = blockIdx.x * 1024 + k * 256 + tid;   // (t,n), n minor
            int t = i >> 10;                             // channel 0..149
            int n = i & (NG - 1);
            int m  = t / 3;
            int cc = t - 3 * m;
            float v = fdc[(((size_t)cid * MM + m) * NG + n) * 3 + cc];
            g_featT[n * ROWF + t + 2 * (t / 38)] = v;    // quarter-padded slot
        }
        return;
    }

    __shared__ __align__(16) float4 s_bb[NG];            // 16 KB
    const int cb = blockIdx.x - TRB;                     // 0..127
#pragma unroll
    for (int j = 0; j < 4; j++) {
        int n = tid + j * 256;
        float cx, cy, c1, c2, c3, op;
        float4 bb;
        project(n, xyz, chol, opac, cx, cy, c1, c2, c3, op, bb);
        s_bb[n] = bb;
        if (cb == 0) {
            float4* p = (float4*)&g_params[n * 8];
            p[0] = make_float4(cx, cy, c1, c2);
            p[1] = make_float4(c3, op, 0.0f, 0.0f);
            float* fr = &g_featT[n * ROWF];              // zero padding slots
            fr[38] = 0.f; fr[39] = 0.f; fr[78] = 0.f; fr[79] = 0.f;
            fr[118] = 0.f; fr[119] = 0.f;
            fr[156] = 0.f; fr[157] = 0.f; fr[158] = 0.f; fr[159] = 0.f;
        }
    }
    if (cb == 0 && tid == 0) g_ticket = 0;               // reset dynamic ticket
    __syncthreads();

    const int lane = tid & 31;
    const int tile = cb * 8 + (tid >> 5);                // one warp per tile
    const float fxl = (float)((tile & (NTX - 1)) * TPX);
    const float fxh = fxl + (float)(TPX - 1);
    const float fyl = (float)((tile >> 4) * TPY);
    const float fyh = fyl + (float)(TPY - 1);
    int off = 0;
#pragma unroll 8
    for (int j = 0; j < NG / 32; j++) {
        int g = j * 32 + lane;
        float4 bb = s_bb[g];
        bool hit = (bb.x <= fxh) && (bb.y >= fxl) && (bb.z <= fyh) && (bb.w >= fyl);
        unsigned m = __ballot_sync(0xffffffffu, hit);
        if (hit) {
            int rank = __popc(m & ((1u << lane) - 1u));
            g_list[tile][off + rank] = (short)g;
        }
        off += __popc(m);
    }
    if (lane == 0) g_count[tile] = off;
}

// ---------------------------------------------------------------------------
// Kernel B: persistent render with alpha-dedup phase.
// Per tile: 16x4 px, 4 threads/pixel (warp-uniform quarter).
// Phase A: each (gaussian, pixel) alpha computed ONCE -> s_alpha.
// Phase B: pure LDS.128 + f32x2 FMA stream.
// ---------------------------------------------------------------------------
__global__ __launch_bounds__(256, 3) void render(float* __restrict__ out) {
    __shared__ __align__(16) float4 s_feat[CHUNK][ROWF / 4];  // 10 KB
    __shared__ __align__(16) float4 s_cp[CHUNK][2];
    __shared__ float s_alpha[CHUNK][64];                      // 4 KB
    __shared__ int   s_tile;

    const int tid = threadIdx.x;
    const int pix = tid & 63;              // 0..63
    const int q   = tid >> 6;              // channel quarter, warp-uniform

    for (;;) {
        if (tid == 0) s_tile = atomicAdd(&g_ticket, 1);
        __syncthreads();
        const int tile = s_tile;
        if (tile >= NTILES) return;

        const int tx0 = (tile & (NTX - 1)) * TPX;
        const int ty0 = (tile >> 4) * TPY;
        const float fx = (float)(tx0 + (pix & (TPX - 1)));
        const float fy = (float)(ty0 + (pix >> 4));
        const int count = g_count[tile];
        const short* __restrict__ list = g_list[tile];

        unsigned long long acc[20];
#pragma unroll
        for (int k = 0; k < 20; k++) acc[k] = 0ull;

        for (int c0 = 0; c0 < count; c0 += CHUNK) {
            int nc = min(CHUNK, count - c0);
            // ---- stage features (nc x 40 float4) + params (nc x 2 float4) ----
            for (int i = tid; i < nc * (ROWF / 4); i += 256) {
                int g = i / (ROWF / 4);
                int k = i - g * (ROWF / 4);
                s_feat[g][k] = ((const float4*)g_featT)[(int)list[c0 + g] * (ROWF / 4) + k];
            }
            if (tid < nc * 2) {
                int g = tid >> 1;
                int k = tid & 1;
                s_cp[g][k] = ((const float4*)g_params)[(int)list[c0 + g] * 2 + k];
            }
            __syncthreads();

            // ---- Phase A: each (g, px) alpha once ----
            for (int i = tid; i < nc * 64; i += 256) {
                int g = i >> 6;
                int p = i & 63;
                float4 P0 = s_cp[g][0];
                float4 P1 = s_cp[g][1];
                float pfx = (float)(tx0 + (p & (TPX - 1)));
                float pfy = (float)(ty0 + (p >> 4));
                float dx = P0.x - pfx;
                float dy = P0.y - pfy;
                float sig = 0.5f * (P0.z * dx * dx + P1.x * dy * dy) + P0.w * dx * dy;
                float al = fminf(0.999f, P1.y * __expf(-sig));
                al = (sig >= 0.0f && al >= (1.0f / 255.0f)) ? al : 0.0f;
                s_alpha[g][p] = al;
            }
            __syncthreads();

            // ---- Phase B: pure LDS + FMA stream ----
            for (int g = 0; g < nc; g++) {
                float al = s_alpha[g][pix];
                unsigned long long ap;
                asm("mov.b64 %0, {%1,%1};" : "=l"(ap) : "r"(__float_as_uint(al)));
                const ulonglong2* fp =
                    (const ulonglong2*)((const float*)&s_feat[g][0] + q * 40);
#pragma unroll
                for (int k = 0; k < 10; k++) {       // 10 x LDS.128 = 20 pairs
                    ulonglong2 f2 = fp[k];
                    asm("fma.rn.f32x2 %0, %1, %2, %0;" : "+l"(acc[2*k])   : "l"(ap), "l"(f2.x));
                    asm("fma.rn.f32x2 %0, %1, %2, %0;" : "+l"(acc[2*k+1]) : "l"(ap), "l"(f2.y));
                }
            }
            __syncthreads();
        }

        // ---- epilogue: pair k -> channels q*38+2k, q*38+2k+1 (k<19 real) ----
        const int pofs = (ty0 + (pix >> 4)) * WW + tx0 + (pix & (TPX - 1));
#pragma unroll
        for (int k = 0; k < 19; k++) {
            int ch = q * 38 + 2 * k;
            if (ch + 1 < NCH) {
                unsigned lo, hi;
                asm("mov.b64 {%0,%1}, %2;" : "=r"(lo), "=r"(hi) : "l"(acc[k]));
                out[(size_t)ch       * NP + pofs] = __uint_as_float(lo);
                out[(size_t)(ch + 1) * NP + pofs] = __uint_as_float(hi);
            }
        }
        __syncthreads();   // protect shared state before next tile
    }
}

// ---------------------------------------------------------------------------
extern "C" void kernel_launch(void* const* d_in, const int* in_sizes, int n_in,
                              void* d_out, int out_size) {
    const float* xyz  = (const float*)d_in[0];  // [N,2]
    const float* chol = (const float*)d_in[1];  // [N,3]
    const float* opac = (const float*)d_in[2];  // [N,1]
    const float* fdc  = (const float*)d_in[3];  // [K,M,N,3]
    const int*   cid  = (const int*)d_in[4];    // scalar

    prep_and_cull<<<TRB + CULLB, 256>>>(xyz, chol, opac, fdc, cid);
    render<<<RGRID, 256>>>((float*)d_out);
}

// round 12
// speedup vs baseline: 1.0143x; 1.0143x over previous
#include <cuda_runtime.h>
#include <cuda_bf16.h>
#include <cstdint>

#define HH   256
#define WW   256
#define NP   (HH * WW)
#define NG   1024
#define MM   50
#define NCH  150
#define ROWF 160                // padded feature row: 4 quarters x 40 floats
#define TPX  16                 // tile width
#define TPY  4                  // tile height
#define NTX  (WW / TPX)         // 16
#define NTY  (HH / TPY)         // 64
#define NTILES (NTX * NTY)      // 1024
#define CHUNK 32                // gaussians staged per chunk
#define TRB  150                // transpose blocks (150*256*4 = 153600)
#define CULLB (NTILES / 16)     // 64 cull blocks (16 tiles each)

// Scratch (device globals; no allocation allowed)
__device__ __align__(16) float g_params[NG * 8];   // cx, cy, c1, c2, c3, op
__device__ __align__(16) float4 g_bbox[NG];        // x0, x1, y0, y1 (float)
__device__ __align__(16) float g_featT[NG * ROWF]; // [n][160] quarter-padded
__device__ short g_list[NTILES][NG];               // per-tile ordered lists
__device__ int   g_count[NTILES];

// ---------------------------------------------------------------------------
// Kernel A: blocks [0,4) project gaussians -> params + bbox + zero feat pads;
//           blocks [4,154) transpose features (4 elems/thread, MLP=4).
// ---------------------------------------------------------------------------
__global__ void prep(const float* __restrict__ xyz,
                     const float* __restrict__ chol,
                     const float* __restrict__ opac,
                     const float* __restrict__ fdc,
                     const int*   __restrict__ cid_p) {
    const int tid = threadIdx.x;
    if (blockIdx.x < 4) {
        int n = blockIdx.x * 256 + tid;
        float2 xr = ((const float2*)xyz)[n];
        float x  = tanhf(xr.x);
        float y  = tanhf(xr.y);
        float l1 = chol[3 * n + 0] + 0.5f;
        float l2 = chol[3 * n + 1];
        float l3 = chol[3 * n + 2] + 0.5f;
        float a = l1 * l1;
        float b = l1 * l2;
        float c = l2 * l2 + l3 * l3;
        float det = a * c - b * b;
        float c1 = c / det;
        float c2 = -b / det;
        float c3 = a / det;
        float cx = 0.5f * ((x + 1.0f) * (float)WW - 1.0f);
        float cy = 0.5f * ((y + 1.0f) * (float)HH - 1.0f);
        float op = opac[n];
        float4* p = (float4*)&g_params[n * 8];
        p[0] = make_float4(cx, cy, c1, c2);
        p[1] = make_float4(c3, op, 0.0f, 0.0f);
        // alpha >= 1/255 <=> sigma <= T = ln(255*op); ellipse extents + margin
        float T = __logf(255.0f * op);
        if (T > 0.0f) {
            float hx = sqrtf(2.0f * T * a) + 2.0f;
            float hy = sqrtf(2.0f * T * c) + 2.0f;
            g_bbox[n] = make_float4(cx - hx, cx + hx, cy - hy, cy + hy);
        } else {
            g_bbox[n] = make_float4(1e9f, -1e9f, 1e9f, -1e9f);
        }
        float* fr = &g_featT[n * ROWF];              // zero padding slots
        fr[38] = 0.f; fr[39] = 0.f; fr[78] = 0.f; fr[79] = 0.f;
        fr[118] = 0.f; fr[119] = 0.f;
        fr[156] = 0.f; fr[157] = 0.f; fr[158] = 0.f; fr[159] = 0.f;
    } else {
        const int cid = *cid_p;
#pragma unroll
        for (int k = 0; k < 4; k++) {
            int i = (blockIdx.x - 4) * 1024 + k * 256 + tid;  // (t,n), n minor
            int t = i >> 10;                                  // channel 0..149
            int n = i & (NG - 1);
            int m  = t / 3;
            int cc = t - 3 * m;
            float v = fdc[(((size_t)cid * MM + m) * NG + n) * 3 + cc];
            g_featT[n * ROWF + t + 2 * (t / 38)] = v;         // quarter-padded
        }
    }
}

// ---------------------------------------------------------------------------
// Kernel B: cull. Each block stages all 1024 bboxes in SMEM (coalesced),
// then 8 warps cull 16 tiles (2 per warp) via LDS + ballot. Ordered output.
// ---------------------------------------------------------------------------
__global__ __launch_bounds__(256) void cull() {
    __shared__ __align__(16) float4 s_bb[NG];        // 16 KB
    const int tid  = threadIdx.x;
    const int lane = tid & 31;
#pragma unroll
    for (int k = 0; k < 4; k++)
        s_bb[k * 256 + tid] = g_bbox[k * 256 + tid];
    __syncthreads();

#pragma unroll
    for (int s = 0; s < 2; s++) {                    // 2 tiles per warp
        int tile = blockIdx.x * 16 + (tid >> 5) * 2 + s;   // < 64*16 = 1024
        const float fxl = (float)((tile & (NTX - 1)) * TPX);
        const float fxh = fxl + (float)(TPX - 1);
        const float fyl = (float)((tile >> 4) * TPY);
        const float fyh = fyl + (float)(TPY - 1);
        int off = 0;
#pragma unroll 4
        for (int j = 0; j < NG / 32; j++) {
            int g = j * 32 + lane;
            float4 bb = s_bb[g];
            bool hit = (bb.x <= fxh) && (bb.y >= fxl) && (bb.z <= fyh) && (bb.w >= fyl);
            unsigned m = __ballot_sync(0xffffffffu, hit);
            if (hit) {
                int rank = __popc(m & ((1u << lane) - 1u));
                g_list[tile][off + rank] = (short)g;
            }
            off += __popc(m);
        }
        if (lane == 0) g_count[tile] = off;
    }
}

// ---------------------------------------------------------------------------
// Kernel C: render. One CTA per 16x4 tile, 4 threads/pixel (warp-uniform
// channel quarter). CHUNK=32 staging (one barrier-pair for most tiles),
// LDS.128 features, float4 params, no per-gaussian ballot.
// ---------------------------------------------------------------------------
__global__ __launch_bounds__(256, 3) void render(float* __restrict__ out) {
    __shared__ __align__(16) float4 s_feat[CHUNK][ROWF / 4];  // 20 KB
    __shared__ __align__(16) float4 s_cp[CHUNK][2];

    const int tid  = threadIdx.x;
    const int tile = blockIdx.x;
    const int tx0  = (tile & (NTX - 1)) * TPX;
    const int ty0  = (tile >> 4) * TPY;

    const int pix = tid & 63;              // 0..63
    const int q   = tid >> 6;              // channel quarter, warp-uniform
    const float fx = (float)(tx0 + (pix & (TPX - 1)));
    const float fy = (float)(ty0 + (pix >> 4));

    const int count = g_count[tile];
    const short* __restrict__ list = g_list[tile];

    unsigned long long acc[20];
#pragma unroll
    for (int k = 0; k < 20; k++) acc[k] = 0ull;

    for (int c0 = 0; c0 < count; c0 += CHUNK) {
        int nc = min(CHUNK, count - c0);
        for (int i = tid; i < nc * (ROWF / 4); i += 256) {
            int g = i / (ROWF / 4);
            int k = i - g * (ROWF / 4);
            s_feat[g][k] = ((const float4*)g_featT)[(int)list[c0 + g] * (ROWF / 4) + k];
        }
        if (tid < nc * 2) {
            int g = tid >> 1;
            int k = tid & 1;
            s_cp[g][k] = ((const float4*)g_params)[(int)list[c0 + g] * 2 + k];
        }
        __syncthreads();

        for (int g = 0; g < nc; g++) {
            float4 P0 = s_cp[g][0];
            float4 P1 = s_cp[g][1];
            float dx = P0.x - fx;
            float dy = P0.y - fy;
            float sig = 0.5f * (P0.z * dx * dx + P1.x * dy * dy) + P0.w * dx * dy;
            float al = fminf(0.999f, P1.y * __expf(-sig));
            al = (sig >= 0.0f && al >= (1.0f / 255.0f)) ? al : 0.0f;
            unsigned long long ap;
            asm("mov.b64 %0, {%1,%1};" : "=l"(ap) : "r"(__float_as_uint(al)));
            const ulonglong2* fp =
                (const ulonglong2*)((const float*)&s_feat[g][0] + q * 40);
#pragma unroll
            for (int k = 0; k < 10; k++) {           // 10 x LDS.128
                ulonglong2 f2 = fp[k];
                asm("fma.rn.f32x2 %0, %1, %2, %0;" : "+l"(acc[2*k])   : "l"(ap), "l"(f2.x));
                asm("fma.rn.f32x2 %0, %1, %2, %0;" : "+l"(acc[2*k+1]) : "l"(ap), "l"(f2.y));
            }
        }
        __syncthreads();
    }

    // ---- epilogue: pair k -> channels 38q+2k, 38q+2k+1 (19 real pairs) ----
    const int pofs = (ty0 + (pix >> 4)) * WW + tx0 + (pix & (TPX - 1));
#pragma unroll
    for (int k = 0; k < 19; k++) {
        int ch = q * 38 + 2 * k;
        if (ch + 1 < NCH) {
            unsigned lo, hi;
            asm("mov.b64 {%0,%1}, %2;" : "=r"(lo), "=r"(hi) : "l"(acc[k]));
            out[(size_t)ch       * NP + pofs] = __uint_as_float(lo);
            out[(size_t)(ch + 1) * NP + pofs] = __uint_as_float(hi);
        }
    }
}

// ---------------------------------------------------------------------------
extern "C" void kernel_launch(void* const* d_in, const int* in_sizes, int n_in,
                              void* d_out, int out_size) {
    const float* xyz  = (const float*)d_in[0];  // [N,2]
    const float* chol = (const float*)d_in[1];  // [N,3]
    const float* opac = (const float*)d_in[2];  // [N,1]
    const float* fdc  = (const float*)d_in[3];  // [K,M,N,3]
    const int*   cid  = (const int*)d_in[4];    // scalar

    prep<<<4 + TRB, 256>>>(xyz, chol, opac, fdc, cid);
    cull<<<CULLB, 256>>>();
    render<<<NTILES, 256>>>((float*)d_out);
}

// round 13
// speedup vs baseline: 1.1924x; 1.1756x over previous
#include <cuda_runtime.h>
#include <cuda_bf16.h>
#include <cstdint>

#define HH   256
#define WW   256
#define NP   (HH * WW)
#define NG   1024
#define MM   50
#define NCH  150
#define ROWF 160                // padded feature row: 4 quarters x 40 floats
#define TPX  16                 // tile width
#define TPY  4                  // tile height
#define NTX  (WW / TPX)         // 16
#define NTY  (HH / TPY)         // 64
#define NTILES (NTX * NTY)      // 1024
#define CHUNK 32                // gaussians staged per chunk
#define TRB  150                // transpose blocks (150*256*4 = 153600)

// Scratch (device globals; no allocation allowed)
__device__ __align__(16) float g_params[NG * 8];   // cx, cy, c1, c2, c3, op
__device__ __align__(16) float4 g_bbox[NG];        // x0, x1, y0, y1 (float)
__device__ __align__(16) float g_featT[NG * ROWF]; // [n][160] quarter-padded

// ---------------------------------------------------------------------------
// Kernel A: blocks [0,4) project gaussians -> params + bbox + zero feat pads;
//           blocks [4,154) transpose features (4 elems/thread, MLP=4).
// ---------------------------------------------------------------------------
__global__ void prep(const float* __restrict__ xyz,
                     const float* __restrict__ chol,
                     const float* __restrict__ opac,
                     const float* __restrict__ fdc,
                     const int*   __restrict__ cid_p) {
    const int tid = threadIdx.x;
    if (blockIdx.x < 4) {
        int n = blockIdx.x * 256 + tid;
        float2 xr = ((const float2*)xyz)[n];
        float x  = tanhf(xr.x);
        float y  = tanhf(xr.y);
        float l1 = chol[3 * n + 0] + 0.5f;
        float l2 = chol[3 * n + 1];
        float l3 = chol[3 * n + 2] + 0.5f;
        float a = l1 * l1;
        float b = l1 * l2;
        float c = l2 * l2 + l3 * l3;
        float det = a * c - b * b;
        float c1 = c / det;
        float c2 = -b / det;
        float c3 = a / det;
        float cx = 0.5f * ((x + 1.0f) * (float)WW - 1.0f);
        float cy = 0.5f * ((y + 1.0f) * (float)HH - 1.0f);
        float op = opac[n];
        float4* p = (float4*)&g_params[n * 8];
        p[0] = make_float4(cx, cy, c1, c2);
        p[1] = make_float4(c3, op, 0.0f, 0.0f);
        // alpha >= 1/255 <=> sigma <= T = ln(255*op); ellipse extents + margin
        float T = __logf(255.0f * op);
        if (T > 0.0f) {
            float hx = sqrtf(2.0f * T * a) + 2.0f;
            float hy = sqrtf(2.0f * T * c) + 2.0f;
            g_bbox[n] = make_float4(cx - hx, cx + hx, cy - hy, cy + hy);
        } else {
            g_bbox[n] = make_float4(1e9f, -1e9f, 1e9f, -1e9f);
        }
        float* fr = &g_featT[n * ROWF];              // zero padding slots
        fr[38] = 0.f; fr[39] = 0.f; fr[78] = 0.f; fr[79] = 0.f;
        fr[118] = 0.f; fr[119] = 0.f;
        fr[156] = 0.f; fr[157] = 0.f; fr[158] = 0.f; fr[159] = 0.f;
    } else {
        const int cid = *cid_p;
#pragma unroll
        for (int k = 0; k < 4; k++) {
            int i = (blockIdx.x - 4) * 1024 + k * 256 + tid;  // (t,n), n minor
            int t = i >> 10;                                  // channel 0..149
            int n = i & (NG - 1);
            int m  = t / 3;
            int cc = t - 3 * m;
            float v = fdc[(((size_t)cid * MM + m) * NG + n) * 3 + cc];
            g_featT[n * ROWF + t + 2 * (t / 38)] = v;         // quarter-padded
        }
    }
}

// ---------------------------------------------------------------------------
// Kernel B: render with in-CTA cull. One CTA per 16x4 tile, 4 threads/pixel
// (warp-uniform channel quarter), CHUNK=32 SMEM staging, LDS.128 streams.
// ---------------------------------------------------------------------------
__global__ __launch_bounds__(256, 3) void render(float* __restrict__ out) {
    __shared__ unsigned s_mask[32];
    __shared__ int      s_off[32];
    __shared__ int      s_count;
    __shared__ short    s_list[NG];                           // 2 KB
    __shared__ __align__(16) float4 s_feat[CHUNK][ROWF / 4];  // 20 KB
    __shared__ __align__(16) float4 s_cp[CHUNK][2];

    const int tid  = threadIdx.x;
    const int lane = tid & 31;
    const int wid  = tid >> 5;
    const int tile = blockIdx.x;
    const int tx0  = (tile & (NTX - 1)) * TPX;
    const int ty0  = (tile >> 4) * TPY;

    // ---- in-CTA cull: 4 coalesced bbox tests/thread, ordered bitmask ----
    const float fxl = (float)tx0, fxh = (float)(tx0 + TPX - 1);
    const float fyl = (float)ty0, fyh = (float)(ty0 + TPY - 1);
#pragma unroll
    for (int j = 0; j < 4; j++) {
        int g = tid + j * 256;                // group index g>>5 = j*8 + wid
        float4 bb = g_bbox[g];
        bool hit = (bb.x <= fxh) && (bb.y >= fxl) && (bb.z <= fyh) && (bb.w >= fyl);
        unsigned m = __ballot_sync(0xffffffffu, hit);
        if (lane == 0) s_mask[j * 8 + wid] = m;
    }
    __syncthreads();
    if (tid < 32) {
        int c = __popc(s_mask[tid]);
        int x = c;
#pragma unroll
        for (int d = 1; d < 32; d <<= 1) {
            int y = __shfl_up_sync(0xffffffffu, x, d);
            if (lane >= d) x += y;
        }
        s_off[tid] = x - c;
        if (tid == 31) s_count = x;
    }
    __syncthreads();
    if (tid < 32) {
        unsigned m = s_mask[tid];
        int o = s_off[tid];
        int base = tid * 32;
        while (m) {
            int b = __ffs(m) - 1;
            m &= m - 1;
            s_list[o++] = (short)(base + b);
        }
    }
    __syncthreads();
    const int count = s_count;

    const int pix = tid & 63;              // 0..63
    const int q   = tid >> 6;              // channel quarter, warp-uniform
    const float fx = (float)(tx0 + (pix & (TPX - 1)));
    const float fy = (float)(ty0 + (pix >> 4));

    unsigned long long acc[20];
#pragma unroll
    for (int k = 0; k < 20; k++) acc[k] = 0ull;

    for (int c0 = 0; c0 < count; c0 += CHUNK) {
        int nc = min(CHUNK, count - c0);
        for (int i = tid; i < nc * (ROWF / 4); i += 256) {
            int g = i / (ROWF / 4);
            int k = i - g * (ROWF / 4);
            s_feat[g][k] = ((const float4*)g_featT)[(int)s_list[c0 + g] * (ROWF / 4) + k];
        }
        if (tid < nc * 2) {
            int g = tid >> 1;
            int k = tid & 1;
            s_cp[g][k] = ((const float4*)g_params)[(int)s_list[c0 + g] * 2 + k];
        }
        __syncthreads();

        for (int g = 0; g < nc; g++) {
            float4 P0 = s_cp[g][0];
            float4 P1 = s_cp[g][1];
            float dx = P0.x - fx;
            float dy = P0.y - fy;
            float sig = 0.5f * (P0.z * dx * dx + P1.x * dy * dy) + P0.w * dx * dy;
            float al = fminf(0.999f, P1.y * __expf(-sig));
            al = (sig >= 0.0f && al >= (1.0f / 255.0f)) ? al : 0.0f;
            unsigned long long ap;
            asm("mov.b64 %0, {%1,%1};" : "=l"(ap) : "r"(__float_as_uint(al)));
            const ulonglong2* fp =
                (const ulonglong2*)((const float*)&s_feat[g][0] + q * 40);
#pragma unroll
            for (int k = 0; k < 10; k++) {           // 10 x LDS.128
                ulonglong2 f2 = fp[k];
                asm("fma.rn.f32x2 %0, %1, %2, %0;" : "+l"(acc[2*k])   : "l"(ap), "l"(f2.x));
                asm("fma.rn.f32x2 %0, %1, %2, %0;" : "+l"(acc[2*k+1]) : "l"(ap), "l"(f2.y));
            }
        }
        __syncthreads();
    }

    // ---- epilogue: pair k -> channels 38q+2k, 38q+2k+1 (19 real pairs) ----
    const int pofs = (ty0 + (pix >> 4)) * WW + tx0 + (pix & (TPX - 1));
#pragma unroll
    for (int k = 0; k < 19; k++) {
        int ch = q * 38 + 2 * k;
        if (ch + 1 < NCH) {
            unsigned lo, hi;
            asm("mov.b64 {%0,%1}, %2;" : "=r"(lo), "=r"(hi) : "l"(acc[k]));
            out[(size_t)ch       * NP + pofs] = __uint_as_float(lo);
            out[(size_t)(ch + 1) * NP + pofs] = __uint_as_float(hi);
        }
    }
}

// ---------------------------------------------------------------------------
extern "C" void kernel_launch(void* const* d_in, const int* in_sizes, int n_in,
                              void* d_out, int out_size) {
    const float* xyz  = (const float*)d_in[0];  // [N,2]
    const float* chol = (const float*)d_in[1];  // [N,3]
    const float* opac = (const float*)d_in[2];  // [N,1]
    const float* fdc  = (const float*)d_in[3];  // [K,M,N,3]
    const int*   cid  = (const int*)d_in[4];    // scalar

    prep<<<4 + TRB, 256>>>(xyz, chol, opac, fdc, cid);
    render<<<NTILES, 256>>>((float*)d_out);
}